// round 1
// baseline (speedup 1.0000x reference)
#include <cuda_runtime.h>

#define VOCAB 100000
#define EMBED 128
#define BATCH 65536
#define KNEG 10
#define WPB 8                  // warps per block
#define NBLOCKS (BATCH / WPB)  // 8192

// Per-block partial sums (deterministic reduction scratch; no allocations).
__device__ float g_partials[NBLOCKS];

__device__ __forceinline__ float warp_bfly_sum(float v) {
#pragma unroll
    for (int m = 16; m; m >>= 1) v += __shfl_xor_sync(0xffffffffu, v, m);
    return v;
}

__global__ void __launch_bounds__(256) sgns_main(
    const float* __restrict__ tW, const float* __restrict__ cW,
    const int* __restrict__ t, const int* __restrict__ c,
    const int* __restrict__ n)
{
    const int lane = threadIdx.x & 31;
    const int wid  = threadIdx.x >> 5;
    const int b    = blockIdx.x * WPB + wid;   // one warp per batch element

    const float4* tw4 = reinterpret_cast<const float4*>(tW);
    const float4* cw4 = reinterpret_cast<const float4*>(cW);

    // Gather vt, vc: each lane owns 4 contiguous floats -> one 512B coalesced tx.
    const float4 vt = tw4[(long)t[b] * 32 + lane];
    const float4 vc = cw4[(long)c[b] * 32 + lane];

    // Issue all negative-row gathers early for MLP (indices are independent).
    int nidx[KNEG];
#pragma unroll
    for (int k = 0; k < KNEG; k++) nidx[k] = n[b * KNEG + k];

    float4 vn[KNEG];
#pragma unroll
    for (int k = 0; k < KNEG; k++) vn[k] = cw4[(long)nidx[k] * 32 + lane];

    // Positive term.
    float pos = vt.x * vc.x + vt.y * vc.y + vt.z * vc.z + vt.w * vc.w;
    pos = warp_bfly_sum(pos);
    float loss = -logf(1.0f / (1.0f + expf(-pos)) + 1e-10f);

    // Negative terms: -log(sigmoid(-s) + eps).
#pragma unroll
    for (int k = 0; k < KNEG; k++) {
        float s = vt.x * vn[k].x + vt.y * vn[k].y + vt.z * vn[k].z + vt.w * vn[k].w;
        s = warp_bfly_sum(s);
        loss += -logf(1.0f / (1.0f + expf(s)) + 1e-10f);
    }

    // Block reduce (loss is replicated across all lanes of the warp).
    __shared__ float sm[WPB];
    if (lane == 0) sm[wid] = loss;
    __syncthreads();
    if (wid == 0) {
        float v = (lane < WPB) ? sm[lane] : 0.0f;
        v += __shfl_xor_sync(0xffffffffu, v, 1);
        v += __shfl_xor_sync(0xffffffffu, v, 2);
        v += __shfl_xor_sync(0xffffffffu, v, 4);
        if (lane == 0) g_partials[blockIdx.x] = v;
    }
}

__global__ void __launch_bounds__(256) sgns_reduce(float* __restrict__ out)
{
    const int lane = threadIdx.x & 31;
    const int wid  = threadIdx.x >> 5;

    float v = 0.0f;
    for (int i = threadIdx.x; i < NBLOCKS; i += 256) v += g_partials[i];
    v = warp_bfly_sum(v);

    __shared__ float sm[8];
    if (lane == 0) sm[wid] = v;
    __syncthreads();
    if (wid == 0) {
        float s = (lane < 8) ? sm[lane] : 0.0f;
        s += __shfl_xor_sync(0xffffffffu, s, 1);
        s += __shfl_xor_sync(0xffffffffu, s, 2);
        s += __shfl_xor_sync(0xffffffffu, s, 4);
        if (lane == 0) out[0] = s / (float)BATCH;
    }
}

extern "C" void kernel_launch(void* const* d_in, const int* in_sizes, int n_in,
                              void* d_out, int out_size)
{
    const float* tW = (const float*)d_in[0];
    const float* cW = (const float*)d_in[1];
    const int*   t  = (const int*)d_in[2];
    const int*   c  = (const int*)d_in[3];
    const int*   n  = (const int*)d_in[4];
    float* out = (float*)d_out;

    sgns_main<<<NBLOCKS, 256>>>(tW, cW, t, c, n);
    sgns_reduce<<<1, 256>>>(out);
}

// round 2
// speedup vs baseline: 1.4915x; 1.4915x over previous
#include <cuda_runtime.h>

#define EMBED   128
#define BATCH   65536
#define KNEG    10
#define TPB     512
#define WPB     (TPB / 32)          // 16 warps per block
#define NBLOCKS (BATCH / WPB)       // 4096

// Deterministic cross-block reduction scratch (no allocations allowed).
__device__ float    g_partials[NBLOCKS];
__device__ unsigned g_count;        // zero-init; self-resets each run

__device__ __forceinline__ float warp_bfly_sum(float v) {
#pragma unroll
    for (int m = 16; m; m >>= 1) v += __shfl_xor_sync(0xffffffffu, v, m);
    return v;
}

__global__ void __launch_bounds__(TPB) sgns_fused(
    const float* __restrict__ tW, const float* __restrict__ cW,
    const int* __restrict__ t, const int* __restrict__ c,
    const int* __restrict__ n, float* __restrict__ out)
{
    const int lane = threadIdx.x & 31;
    const int wid  = threadIdx.x >> 5;
    const int b    = blockIdx.x * WPB + wid;     // one warp per batch element

    const float4* tw4 = reinterpret_cast<const float4*>(tW);
    const float4* cw4 = reinterpret_cast<const float4*>(cW);

    // Row gathers: lane owns a float4 slice -> one coalesced 512B warp tx per row.
    const float4 vt = tw4[(unsigned)t[b] * 32u + lane];
    const float4 vc = cw4[(unsigned)c[b] * 32u + lane];

    int nidx[KNEG];
#pragma unroll
    for (int k = 0; k < KNEG; k++) nidx[k] = n[b * KNEG + k];

    float4 vn[KNEG];                 // 10 independent loads in flight (MLP)
#pragma unroll
    for (int k = 0; k < KNEG; k++) vn[k] = cw4[(unsigned)nidx[k] * 32u + lane];

    // Per-lane score partials. s[0] = -pos_score so every term is softplus(s).
    float s[KNEG + 1];
    s[0] = -(vt.x * vc.x + vt.y * vc.y + vt.z * vc.z + vt.w * vc.w);
#pragma unroll
    for (int k = 0; k < KNEG; k++)
        s[k + 1] = vt.x * vn[k].x + vt.y * vn[k].y + vt.z * vn[k].z + vt.w * vn[k].w;

    // Warp reductions: full sums land on all lanes.
#pragma unroll
    for (int k = 0; k < KNEG + 1; k++) s[k] = warp_bfly_sum(s[k]);

    // loss_b = sum_k softplus(s_k) = log( prod_k (1 + e^{s_k}) )
    // (eps=1e-10 inside the reference's log is negligible: sigmoid ~ 0.5 here)
    float P = 1.0f;
#pragma unroll
    for (int k = 0; k < KNEG + 1; k++) {
        float u = __expf(s[k]);      // FMUL + MUFU.EX2
        P = fmaf(P, u, P);           // P *= (1 + u)
    }
    const float loss = __logf(P);    // single MUFU.LG2 per warp

    // Block reduce (loss replicated across lanes; take lane 0 per warp).
    __shared__ float sm[WPB];
    if (lane == 0) sm[wid] = loss;
    __syncthreads();
    if (wid == 0) {
        float v = (lane < WPB) ? sm[lane] : 0.0f;
        v += __shfl_xor_sync(0xffffffffu, v, 8);
        v += __shfl_xor_sync(0xffffffffu, v, 4);
        v += __shfl_xor_sync(0xffffffffu, v, 2);
        v += __shfl_xor_sync(0xffffffffu, v, 1);
        if (lane == 0) g_partials[blockIdx.x] = v;
    }

    // ---- Fused final reduction: last block to arrive sums all partials ----
    __shared__ bool isLast;
    if (threadIdx.x == 0) {
        __threadfence();                         // publish g_partials[blockIdx.x]
        unsigned prev = atomicAdd(&g_count, 1u);
        isLast = (prev == (unsigned)(gridDim.x - 1));
    }
    __syncthreads();

    if (isLast) {
        // All other blocks fenced before their atomic -> partials visible.
        const volatile float* vp = g_partials;
        float v = 0.0f;
        for (int i = threadIdx.x; i < NBLOCKS; i += TPB) v += vp[i];
        v = warp_bfly_sum(v);
        if (lane == 0) sm[wid] = v;
        __syncthreads();
        if (wid == 0) {
            float tot = (lane < WPB) ? sm[lane] : 0.0f;
            tot += __shfl_xor_sync(0xffffffffu, tot, 8);
            tot += __shfl_xor_sync(0xffffffffu, tot, 4);
            tot += __shfl_xor_sync(0xffffffffu, tot, 2);
            tot += __shfl_xor_sync(0xffffffffu, tot, 1);
            if (lane == 0) {
                out[0] = tot * (1.0f / (float)BATCH);
                g_count = 0;                     // reset for next graph replay
            }
        }
    }
}

extern "C" void kernel_launch(void* const* d_in, const int* in_sizes, int n_in,
                              void* d_out, int out_size)
{
    const float* tW = (const float*)d_in[0];
    const float* cW = (const float*)d_in[1];
    const int*   t  = (const int*)d_in[2];
    const int*   c  = (const int*)d_in[3];
    const int*   n  = (const int*)d_in[4];
    float* out = (float*)d_out;

    sgns_fused<<<NBLOCKS, TPB>>>(tW, cW, t, c, n, out);
}

// round 3
// speedup vs baseline: 1.4996x; 1.0054x over previous
#include <cuda_runtime.h>

#define EMBED   128
#define BATCH   65536
#define KNEG    10
#define NVAL    16                  // 11 real scores padded to 16
#define TPB     512
#define WPB     (TPB / 32)          // 16 warps per block
#define NBLOCKS (BATCH / WPB)       // 4096

#define LN2     0.69314718055994530942f

// Deterministic cross-block reduction scratch (no allocations allowed).
__device__ float    g_partials[NBLOCKS];
__device__ unsigned g_count;        // zero-init; self-resets each replay

// Pair two per-lane value-partials into one register: after this, lanes with
// (lane & bit)==0 carry u's partial (now summed over the bit-pair), the others
// carry v's. Repeated over bits 16,8,4,2 this packs 16 values into 1 register.
__device__ __forceinline__ float pair_step(float u, float v, int bit, bool sel) {
    float x = sel ? v : u;                       // value this lane keeps
    float y = sel ? u : v;                       // value the partner lane keeps
    return x + __shfl_xor_sync(0xffffffffu, y, bit);
}

__global__ void __launch_bounds__(TPB) sgns_fused(
    const float* __restrict__ tW, const float* __restrict__ cW,
    const int* __restrict__ t, const int* __restrict__ c,
    const int* __restrict__ n, float* __restrict__ out)
{
    const int lane = threadIdx.x & 31;
    const int wid  = threadIdx.x >> 5;
    const int b    = blockIdx.x * WPB + wid;     // one warp per batch element

    const float4* tw4 = reinterpret_cast<const float4*>(tW);
    const float4* cw4 = reinterpret_cast<const float4*>(cW);

    // Negative indices: 40B contiguous, 8B aligned -> 5 broadcast int2 loads.
    int nidx[KNEG];
    {
        const int2* n2 = reinterpret_cast<const int2*>(n + b * KNEG);
#pragma unroll
        for (int j = 0; j < 5; j++) {
            int2 p = n2[j];
            nidx[2 * j]     = p.x;
            nidx[2 * j + 1] = p.y;
        }
    }

    // Row gathers (512B fully-coalesced warp tx each). L1 temporal reuse is
    // ~0 for random gathers over a 51MB table -> stream through L1 (.cg).
    const float4 vt = __ldcg(&tw4[(unsigned)t[b] * 32u + lane]);
    const float4 vc = __ldcg(&cw4[(unsigned)c[b] * 32u + lane]);
    float4 vn[KNEG];
#pragma unroll
    for (int k = 0; k < KNEG; k++)
        vn[k] = __ldcg(&cw4[(unsigned)nidx[k] * 32u + lane]);

    // Per-lane score partials; s[0] = -pos so every term is softplus(s).
    float s[NVAL];
    s[0] = -(vt.x * vc.x + vt.y * vc.y + vt.z * vc.z + vt.w * vc.w);
#pragma unroll
    for (int k = 0; k < KNEG; k++)
        s[k + 1] = vt.x * vn[k].x + vt.y * vn[k].y + vt.z * vn[k].z + vt.w * vn[k].w;
#pragma unroll
    for (int k = KNEG + 1; k < NVAL; k++) s[k] = 0.0f;   // padding (softplus(0)=ln2)

    // Packed pairing-tree reduction: 16 values x 32 lanes -> each lane ends
    // holding the FULL sum of one value (each value lives in exactly 2 lanes).
    const bool b16 = lane & 16, b8 = lane & 8, b4 = lane & 4, b2 = lane & 2;
    float r1[8], r2[4], r3[2], r4;
#pragma unroll
    for (int j = 0; j < 8; j++) r1[j] = pair_step(s[2*j],  s[2*j+1],  16, b16);
#pragma unroll
    for (int j = 0; j < 4; j++) r2[j] = pair_step(r1[2*j], r1[2*j+1],  8, b8);
#pragma unroll
    for (int j = 0; j < 2; j++) r3[j] = pair_step(r2[2*j], r2[2*j+1],  4, b4);
    r4 = pair_step(r3[0], r3[1], 2, b2);
    r4 += __shfl_xor_sync(0xffffffffu, r4, 1);   // finish the lane-pair dim

    // One softplus per lane (instead of 11 per lane, lane-replicated).
    float sp = __logf(1.0f + __expf(r4));

    // Lane sum = 2 * (sum_{11 real} softplus + 5*ln2).
#pragma unroll
    for (int m = 16; m; m >>= 1) sp += __shfl_xor_sync(0xffffffffu, sp, m);
    const float loss = 0.5f * sp - 5.0f * LN2;

    // Block reduce.
    __shared__ float sm[WPB];
    if (lane == 0) sm[wid] = loss;
    __syncthreads();
    if (wid == 0) {
        float v = (lane < WPB) ? sm[lane] : 0.0f;
        v += __shfl_xor_sync(0xffffffffu, v, 8);
        v += __shfl_xor_sync(0xffffffffu, v, 4);
        v += __shfl_xor_sync(0xffffffffu, v, 2);
        v += __shfl_xor_sync(0xffffffffu, v, 1);
        if (lane == 0) g_partials[blockIdx.x] = v;
    }

    // Fused final reduction: last block to arrive sums all partials.
    __shared__ bool isLast;
    if (threadIdx.x == 0) {
        __threadfence();
        unsigned prev = atomicAdd(&g_count, 1u);
        isLast = (prev == (unsigned)(gridDim.x - 1));
    }
    __syncthreads();

    if (isLast) {
        const volatile float* vp = g_partials;
        float v = 0.0f;
        for (int i = threadIdx.x; i < NBLOCKS; i += TPB) v += vp[i];
#pragma unroll
        for (int m = 16; m; m >>= 1) v += __shfl_xor_sync(0xffffffffu, v, m);
        if (lane == 0) sm[wid] = v;
        __syncthreads();
        if (wid == 0) {
            float tot = (lane < WPB) ? sm[lane] : 0.0f;
            tot += __shfl_xor_sync(0xffffffffu, tot, 8);
            tot += __shfl_xor_sync(0xffffffffu, tot, 4);
            tot += __shfl_xor_sync(0xffffffffu, tot, 2);
            tot += __shfl_xor_sync(0xffffffffu, tot, 1);
            if (lane == 0) {
                out[0] = tot * (1.0f / (float)BATCH);
                g_count = 0;                     // reset for next graph replay
            }
        }
    }
}

extern "C" void kernel_launch(void* const* d_in, const int* in_sizes, int n_in,
                              void* d_out, int out_size)
{
    const float* tW = (const float*)d_in[0];
    const float* cW = (const float*)d_in[1];
    const int*   t  = (const int*)d_in[2];
    const int*   c  = (const int*)d_in[3];
    const int*   n  = (const int*)d_in[4];
    float* out = (float*)d_out;

    sgns_fused<<<NBLOCKS, TPB>>>(tW, cW, t, c, n, out);
}